// round 2
// baseline (speedup 1.0000x reference)
#include <cuda_runtime.h>
#include <math.h>
#include <stdint.h>

// ---------------------------------------------------------------------------
// Problem constants (shapes fixed by the reference)
// ---------------------------------------------------------------------------
constexpr int NNODE  = 50000;
constexpr int HCMAX  = 256;    // max feature width (4 heads * 64)
constexpr int NHMAX  = 4;

// ---------------------------------------------------------------------------
// Scratch (device globals: allocation-free)
// ---------------------------------------------------------------------------
__device__ __align__(16) float g_h  [(size_t)NNODE * HCMAX];  // h = A @ W
__device__ __align__(16) float g_out[(size_t)NNODE * HCMAX];  // aggregation / layer output
__device__ __align__(16) float g_asn[NNODE * NHMAX];          // alpha_src per node,head
__device__ __align__(16) float g_adn[NNODE * NHMAX];          // alpha_dst per node,head
__device__ __align__(16) float g_m  [NNODE * NHMAX];          // segment max
__device__ __align__(16) float g_sumw[NNODE * NHMAX];         // softmax denom
__device__ __align__(16) float g_colsum[HCMAX];
__device__ __align__(16) float g_colsq [HCMAX];
__device__ __align__(16) float g_scale [HCMAX];               // BN scale (fused into next GEMM)
__device__ __align__(16) float g_shift [HCMAX];               // BN shift

// ---------------------------------------------------------------------------
// Helpers
// ---------------------------------------------------------------------------
__device__ __forceinline__ void atomicMaxF(float* addr, float v) {
    if (v >= 0.f) atomicMax((int*)addr, __float_as_int(v));
    else          atomicMin((unsigned int*)addr, __float_as_uint(v));
}

__device__ __forceinline__ void red_add_v4(float* p, float a, float b, float c, float d) {
    asm volatile("red.global.add.v4.f32 [%0], {%1, %2, %3, %4};"
                 :: "l"(p), "f"(a), "f"(b), "f"(c), "f"(d) : "memory");
}
__device__ __forceinline__ void red_add_v2(float* p, float a, float b) {
    asm volatile("red.global.add.v2.f32 [%0], {%1, %2};"
                 :: "l"(p), "f"(a), "f"(b) : "memory");
}

// ---------------------------------------------------------------------------
// K1: SGEMM  g_h[M,Ncols] = A[M,K] @ W[K,Ncols]
//     src==1: A = g_out with fused BN (scale/shift per column) + ReLU on load
//     src==0: A = Ain (raw x)
// ---------------------------------------------------------------------------
#define BM 128
#define BN 128
#define BK 8
#define TM 8
#define TN 8

__global__ __launch_bounds__(256)
void sgemm_kernel(const float* __restrict__ Ain, const float* __restrict__ W,
                  int M, int K, int Ncols, int src) {
    __shared__ float As[BK][BM + 4];
    __shared__ float Bs[BK][BN + 4];

    const float* A = src ? g_out : Ain;

    const int tid = threadIdx.x;
    const int tx  = tid & 15;          // 16 cols of threads
    const int ty  = tid >> 4;          // 16 rows of threads
    const int rowBase = blockIdx.y * BM;
    const int colBase = blockIdx.x * BN;

    float acc[TM][TN];
    #pragma unroll
    for (int i = 0; i < TM; i++)
        #pragma unroll
        for (int j = 0; j < TN; j++) acc[i][j] = 0.f;

    for (int k0 = 0; k0 < K; k0 += BK) {
        // load A tile (BM x BK = 1024 elems, 4/thread)
        #pragma unroll
        for (int i = 0; i < 4; i++) {
            int idx = tid + i * 256;
            int r = idx >> 3;          // 0..127
            int c = idx & 7;           // 0..7
            int gr = rowBase + r;
            int gk = k0 + c;
            float v = 0.f;
            if (gr < M) {
                v = A[(size_t)gr * K + gk];
                if (src) v = fmaxf(0.f, fmaf(v, g_scale[gk], g_shift[gk]));
            }
            As[c][r] = v;
        }
        // load B tile (BK x BN = 1024 elems, 4/thread)
        #pragma unroll
        for (int i = 0; i < 4; i++) {
            int idx = tid + i * 256;
            int r = idx >> 7;          // 0..7
            int c = idx & 127;         // 0..127
            int gc = colBase + c;
            Bs[r][c] = (gc < Ncols) ? W[(size_t)(k0 + r) * Ncols + gc] : 0.f;
        }
        __syncthreads();

        #pragma unroll
        for (int k = 0; k < BK; k++) {
            float a[TM], b[TN];
            #pragma unroll
            for (int i = 0; i < TM; i++) a[i] = As[k][ty * TM + i];
            #pragma unroll
            for (int j = 0; j < TN; j++) b[j] = Bs[k][tx * TN + j];
            #pragma unroll
            for (int i = 0; i < TM; i++)
                #pragma unroll
                for (int j = 0; j < TN; j++) acc[i][j] = fmaf(a[i], b[j], acc[i][j]);
        }
        __syncthreads();
    }

    #pragma unroll
    for (int i = 0; i < TM; i++) {
        int gr = rowBase + ty * TM + i;
        if (gr >= M) continue;
        #pragma unroll
        for (int j = 0; j < TN; j++) {
            int gc = colBase + tx * TN + j;
            if (gc < Ncols) g_h[(size_t)gr * Ncols + gc] = acc[i][j];
        }
    }
}

// ---------------------------------------------------------------------------
// K2: per-(node,head) attention scalars  asn = <h, a_s>,  adn = <h, a_d>
// ---------------------------------------------------------------------------
__global__ void alpha_kernel(const float* __restrict__ a_s, const float* __restrict__ a_d,
                             int M, int H) {
    int idx = blockIdx.x * blockDim.x + threadIdx.x;   // n*H + h
    if (idx >= M * H) return;
    int hh = idx % H;
    int n  = idx / H;
    const float4* hp = (const float4*)(g_h + (size_t)n * H * 64 + hh * 64);
    const float4* ap = (const float4*)(a_s + hh * 64);
    const float4* dp = (const float4*)(a_d + hh * 64);
    float s = 0.f, d = 0.f;
    #pragma unroll
    for (int i = 0; i < 16; i++) {
        float4 h4 = hp[i], a4 = ap[i], d4 = dp[i];
        s += h4.x * a4.x + h4.y * a4.y + h4.z * a4.z + h4.w * a4.w;
        d += h4.x * d4.x + h4.y * d4.y + h4.z * d4.z + h4.w * d4.w;
    }
    g_asn[idx] = s;
    g_adn[idx] = d;
}

// ---------------------------------------------------------------------------
// K3: init accumulators (g_out=0 via float4, m=-inf, sumw=0, col stats=0)
// ---------------------------------------------------------------------------
__global__ void init_kernel(size_t tot4, int NHtot, int HC) {
    size_t i = (size_t)blockIdx.x * blockDim.x + threadIdx.x;
    if (i < tot4) ((float4*)g_out)[i] = make_float4(0.f, 0.f, 0.f, 0.f);
    if (i < (size_t)NHtot) {
        g_m[i]    = __int_as_float(0xff800000);  // -inf
        g_sumw[i] = 0.f;
    }
    if (i < (size_t)HC) { g_colsum[i] = 0.f; g_colsq[i] = 0.f; }
}

// ---------------------------------------------------------------------------
// K4: segment max of leaky_relu(asn[src]+adn[dst]) over incoming edges
// ---------------------------------------------------------------------------
template<int H>
__global__ void edge_max_kernel(const int* __restrict__ ei, int E, int Etot) {
    int e = blockIdx.x * blockDim.x + threadIdx.x;
    if (e >= Etot) return;
    int src, dst;
    if (e < E) { src = ei[e]; dst = ei[E + e]; }
    else       { src = e - E; dst = src; }
    if constexpr (H == 4) {
        float4 s4 = *(const float4*)(g_asn + src * 4);
        float4 d4 = *(const float4*)(g_adn + dst * 4);
        float v0 = s4.x + d4.x, v1 = s4.y + d4.y, v2 = s4.z + d4.z, v3 = s4.w + d4.w;
        v0 = v0 > 0.f ? v0 : 0.2f * v0;
        v1 = v1 > 0.f ? v1 : 0.2f * v1;
        v2 = v2 > 0.f ? v2 : 0.2f * v2;
        v3 = v3 > 0.f ? v3 : 0.2f * v3;
        atomicMaxF(&g_m[dst * 4 + 0], v0);
        atomicMaxF(&g_m[dst * 4 + 1], v1);
        atomicMaxF(&g_m[dst * 4 + 2], v2);
        atomicMaxF(&g_m[dst * 4 + 3], v3);
    } else {
        float v = g_asn[src] + g_adn[dst];
        v = v > 0.f ? v : 0.2f * v;
        atomicMaxF(&g_m[dst], v);
    }
}

// ---------------------------------------------------------------------------
// K5: edge accumulation. warp/edge: w = exp(e - m[dst]); sumw += w;
//     g_out[dst] += w * h[src]  (vectorized red)
// ---------------------------------------------------------------------------
template<int HC, int H>
__global__ __launch_bounds__(256)
void edge_acc_kernel(const int* __restrict__ ei, int E, int Etot) {
    int gw   = (blockIdx.x * 256 + threadIdx.x) >> 5;
    int lane = threadIdx.x & 31;
    if (gw >= Etot) return;
    int src, dst;
    if (gw < E) { src = ei[gw]; dst = ei[E + gw]; }
    else        { src = gw - E; dst = src; }

    float w = 0.f;
    if (lane < H) {
        float ev = g_asn[src * H + lane] + g_adn[dst * H + lane];
        ev = ev > 0.f ? ev : 0.2f * ev;
        w = __expf(ev - g_m[dst * H + lane]);
        atomicAdd(&g_sumw[dst * H + lane], w);
    }
    constexpr int F = HC / 32;                 // floats per lane: 8 or 2
    int head = (lane * F) >> 6;                // C = 64
    float wl = __shfl_sync(0xffffffffu, w, head);

    const float* hs = g_h  + (size_t)src * HC + lane * F;
    float*       op = g_out + (size_t)dst * HC + lane * F;
    if constexpr (F == 8) {
        float4 v0 = *(const float4*)hs;
        float4 v1 = *(const float4*)(hs + 4);
        red_add_v4(op,     v0.x * wl, v0.y * wl, v0.z * wl, v0.w * wl);
        red_add_v4(op + 4, v1.x * wl, v1.y * wl, v1.z * wl, v1.w * wl);
    } else {
        float2 v = *(const float2*)hs;
        red_add_v2(op, v.x * wl, v.y * wl);
    }
}

// ---------------------------------------------------------------------------
// K6: finalize: out = acc/sumw + bias; accumulate BN column stats
//     (block handles 32 nodes; each thread owns a fixed column since 256%HC==0)
// ---------------------------------------------------------------------------
__global__ __launch_bounds__(256)
void finalize_kernel(const float* __restrict__ bias, int M, int H, int HC) {
    int base = blockIdx.x * 32;
    int t = threadIdx.x;
    int c = t % HC;
    float ls = 0.f, lq = 0.f;
    for (int i = t; i < 32 * HC; i += 256) {
        int n = base + i / HC;
        if (n < M) {
            size_t off = (size_t)n * HC + c;
            float v = g_out[off] / g_sumw[n * H + (c >> 6)] + bias[c];
            g_out[off] = v;
            ls += v;
            lq += v * v;
        }
    }
    atomicAdd(&g_colsum[c], ls);
    atomicAdd(&g_colsq[c], lq);
}

// ---------------------------------------------------------------------------
// K7: BN statistics -> per-column scale/shift (consumed by next GEMM / MLP)
// ---------------------------------------------------------------------------
__global__ void bnstats_kernel(const float* __restrict__ gamma,
                               const float* __restrict__ beta, int M, int HC) {
    int c = threadIdx.x;
    if (c >= HC) return;
    float invM  = 1.f / (float)M;
    float mean  = g_colsum[c] * invM;
    float var   = g_colsq[c] * invM - mean * mean;
    float s     = gamma[c] * rsqrtf(var + 1e-5f);
    g_scale[c]  = s;
    g_shift[c]  = beta[c] - mean * s;
}

// ---------------------------------------------------------------------------
// K8: MLP head. warp/node: BN+ReLU(64) -> 32 (ReLU) -> 2
// ---------------------------------------------------------------------------
__global__ __launch_bounds__(256)
void mlp_kernel(const float* __restrict__ hw1, const float* __restrict__ hb1,
                const float* __restrict__ hw2, const float* __restrict__ hb2,
                float* __restrict__ out, int M) {
    __shared__ float sh[8][66];
    int w    = threadIdx.x >> 5;
    int lane = threadIdx.x & 31;
    int n    = blockIdx.x * 8 + w;
    if (n >= M) return;

    int c0 = lane * 2;
    float2 f = *(const float2*)(g_out + (size_t)n * 64 + c0);
    sh[w][c0]     = fmaxf(0.f, fmaf(f.x, g_scale[c0],     g_shift[c0]));
    sh[w][c0 + 1] = fmaxf(0.f, fmaf(f.y, g_scale[c0 + 1], g_shift[c0 + 1]));
    __syncwarp();

    float hj = hb1[lane];
    #pragma unroll
    for (int k = 0; k < 64; k++) hj = fmaf(sh[w][k], hw1[k * 32 + lane], hj);
    hj = fmaxf(hj, 0.f);

    float o0 = hj * hw2[lane * 2];
    float o1 = hj * hw2[lane * 2 + 1];
    #pragma unroll
    for (int off = 16; off; off >>= 1) {
        o0 += __shfl_down_sync(0xffffffffu, o0, off);
        o1 += __shfl_down_sync(0xffffffffu, o1, off);
    }
    if (lane == 0) {
        out[n * 2]     = o0 + hb2[0];
        out[n * 2 + 1] = o1 + hb2[1];
    }
}

// ---------------------------------------------------------------------------
// Host launcher (graph-capturable: kernel launches only, default stream)
// ---------------------------------------------------------------------------
extern "C" void kernel_launch(void* const* d_in, const int* in_sizes, int n_in,
                              void* d_out, int out_size) {
    const float* x  = (const float*)d_in[0];
    const int*   ei = (const int*)d_in[1];
    const int M    = in_sizes[0] / 128;     // 50000
    const int E    = in_sizes[1] / 2;       // 400000
    const int Etot = E + M;                 // with self-loops

    for (int l = 0; l < 4; l++) {
        const float* W  = (const float*)d_in[2 + l * 6 + 0];
        const float* as = (const float*)d_in[2 + l * 6 + 1];
        const float* ad = (const float*)d_in[2 + l * 6 + 2];
        const float* b  = (const float*)d_in[2 + l * 6 + 3];
        const float* gg = (const float*)d_in[2 + l * 6 + 4];
        const float* be = (const float*)d_in[2 + l * 6 + 5];
        const int H  = (l < 3) ? 4 : 1;
        const int HC = H * 64;
        const int K  = (l == 0) ? 128 : 256;

        dim3 ggrid((HC + BN - 1) / BN, (M + BM - 1) / BM);
        sgemm_kernel<<<ggrid, 256>>>(x, W, M, K, HC, l > 0 ? 1 : 0);

        alpha_kernel<<<(M * H + 255) / 256, 256>>>(as, ad, M, H);

        size_t tot4 = (size_t)M * HC / 4;
        init_kernel<<<(unsigned)((tot4 + 255) / 256), 256>>>(tot4, M * H, HC);

        if (l < 3) edge_max_kernel<4><<<(Etot + 255) / 256, 256>>>(ei, E, Etot);
        else       edge_max_kernel<1><<<(Etot + 255) / 256, 256>>>(ei, E, Etot);

        if (l < 3) edge_acc_kernel<256, 4><<<(Etot + 7) / 8, 256>>>(ei, E, Etot);
        else       edge_acc_kernel<64, 1><<<(Etot + 7) / 8, 256>>>(ei, E, Etot);

        finalize_kernel<<<(M + 31) / 32, 256>>>(b, M, H, HC);
        bnstats_kernel<<<1, 256>>>(gg, be, M, HC);
    }

    mlp_kernel<<<(M + 7) / 8, 256>>>((const float*)d_in[26], (const float*)d_in[27],
                                     (const float*)d_in[28], (const float*)d_in[29],
                                     (float*)d_out, M);
}

// round 3
// speedup vs baseline: 1.2386x; 1.2386x over previous
#include <cuda_runtime.h>
#include <math.h>
#include <stdint.h>

// ---------------------------------------------------------------------------
// Problem constants
// ---------------------------------------------------------------------------
constexpr int NNODE  = 50000;
constexpr int HCMAX  = 256;
constexpr int ETOTMAX = 450000;   // E + self-loops

// ---------------------------------------------------------------------------
// Scratch (device globals)
// ---------------------------------------------------------------------------
__device__ __align__(16) float g_h  [(size_t)NNODE * HCMAX];
__device__ __align__(16) float g_out[(size_t)NNODE * HCMAX];
__device__ __align__(16) float g_asn[NNODE * 4];
__device__ __align__(16) float g_adn[NNODE * 4];
__device__ __align__(16) float g_colsum[HCMAX];
__device__ __align__(16) float g_colsq [HCMAX];
__device__ __align__(16) float g_scale [HCMAX];
__device__ __align__(16) float g_shift [HCMAX];
// CSR (built once per launch; graph is layer-invariant)
__device__ int g_cnt   [NNODE];
__device__ int g_rowptr[NNODE + 1];
__device__ int g_cursor[NNODE];
__device__ int g_csrsrc[ETOTMAX];

// ---------------------------------------------------------------------------
// CSR build: count -> scan -> fill
// ---------------------------------------------------------------------------
__global__ void csr_zero(int M) {
    int i = blockIdx.x * blockDim.x + threadIdx.x;
    if (i < M) g_cnt[i] = 0;
}

__global__ void csr_count(const int* __restrict__ ei, int E, int Etot) {
    int e = blockIdx.x * blockDim.x + threadIdx.x;
    if (e >= Etot) return;
    int dst = (e < E) ? ei[E + e] : (e - E);
    atomicAdd(&g_cnt[dst], 1);
}

__global__ void csr_scan(int M, int Etot) {
    __shared__ int sh[1024];
    int t = threadIdx.x;
    int C = (M + 1023) / 1024;
    int lo = t * C, hi = min(lo + C, M);
    int s = 0;
    for (int i = lo; i < hi; i++) s += g_cnt[i];
    sh[t] = s;
    __syncthreads();
    for (int off = 1; off < 1024; off <<= 1) {
        int v = (t >= off) ? sh[t - off] : 0;
        __syncthreads();
        sh[t] += v;
        __syncthreads();
    }
    int run = (t == 0) ? 0 : sh[t - 1];
    for (int i = lo; i < hi; i++) {
        g_rowptr[i] = run;
        g_cursor[i] = run;
        run += g_cnt[i];
    }
    if (t == 0) g_rowptr[M] = Etot;
}

__global__ void csr_fill(const int* __restrict__ ei, int E, int Etot) {
    int e = blockIdx.x * blockDim.x + threadIdx.x;
    if (e >= Etot) return;
    int src, dst;
    if (e < E) { src = ei[e]; dst = ei[E + e]; }
    else       { src = e - E; dst = src; }
    int pos = atomicAdd(&g_cursor[dst], 1);
    g_csrsrc[pos] = src;
}

// ---------------------------------------------------------------------------
// K1: SGEMM  g_h[M,Ncols] = A[M,K] @ W[K,Ncols]
//     srcflag==1: A = g_out with fused BN scale/shift + ReLU on load
//     Double-buffered smem, float4 loads, register-staged pipeline.
// ---------------------------------------------------------------------------
#define BM 128
#define BN 128
#define BK 16

__global__ __launch_bounds__(256)
void sgemm_kernel(const float* __restrict__ Ain, const float* __restrict__ W,
                  int M, int K, int Ncols, int srcflag) {
    __shared__ float As[2][BK][BM + 4];   // stride 132: 16B-aligned rows, <=2-way STS conflict
    __shared__ float Bs[2][BK][BN];

    const float* __restrict__ Aptr = srcflag ? g_out : Ain;

    const int tid = threadIdx.x;
    const int tx  = tid & 15;
    const int ty  = tid >> 4;
    const int rowBase = blockIdx.y * BM;
    const int colBase = blockIdx.x * BN;

    float4 ra0, ra1, rb0, rb1;

#define SGEMM_LDG_ONE(IDX, RA, RB) do {                                         \
        int idx = (IDX);                                                        \
        int ar = idx >> 2, ak = (idx & 3) * 4;                                  \
        int gr = rowBase + ar, gk = k0_ + ak;                                   \
        float4 v = make_float4(0.f, 0.f, 0.f, 0.f);                             \
        if (gr < M) v = *(const float4*)(Aptr + (size_t)gr * K + gk);           \
        if (srcflag) {                                                          \
            float4 sc = *(const float4*)(g_scale + gk);                         \
            float4 sf = *(const float4*)(g_shift + gk);                         \
            v.x = fmaxf(0.f, fmaf(v.x, sc.x, sf.x));                            \
            v.y = fmaxf(0.f, fmaf(v.y, sc.y, sf.y));                            \
            v.z = fmaxf(0.f, fmaf(v.z, sc.z, sf.z));                            \
            v.w = fmaxf(0.f, fmaf(v.w, sc.w, sf.w));                            \
        }                                                                       \
        RA = v;                                                                 \
        int br = idx >> 5, bc = (idx & 31) * 4;                                 \
        int gc = colBase + bc;                                                  \
        float4 bv = make_float4(0.f, 0.f, 0.f, 0.f);                            \
        if (gc < Ncols) bv = *(const float4*)(W + (size_t)(k0_ + br) * Ncols + gc); \
        RB = bv;                                                                \
    } while (0)

#define SGEMM_LDG(K0) do { int k0_ = (K0);                                      \
        SGEMM_LDG_ONE(tid,       ra0, rb0);                                     \
        SGEMM_LDG_ONE(tid + 256, ra1, rb1);                                     \
    } while (0)

#define SGEMM_STS_ONE(BUF, IDX, RA, RB) do {                                    \
        int idx = (IDX);                                                        \
        int ar = idx >> 2, ak = (idx & 3) * 4;                                  \
        As[BUF][ak + 0][ar] = RA.x;                                             \
        As[BUF][ak + 1][ar] = RA.y;                                             \
        As[BUF][ak + 2][ar] = RA.z;                                             \
        As[BUF][ak + 3][ar] = RA.w;                                             \
        int br = idx >> 5, bc = (idx & 31) * 4;                                 \
        *(float4*)&Bs[BUF][br][bc] = RB;                                        \
    } while (0)

#define SGEMM_STS(BUF) do {                                                     \
        SGEMM_STS_ONE(BUF, tid,       ra0, rb0);                                \
        SGEMM_STS_ONE(BUF, tid + 256, ra1, rb1);                                \
    } while (0)

    float acc[8][8];
    #pragma unroll
    for (int i = 0; i < 8; i++)
        #pragma unroll
        for (int j = 0; j < 8; j++) acc[i][j] = 0.f;

    const int nk = K / BK;
    SGEMM_LDG(0);
    SGEMM_STS(0);
    __syncthreads();

    for (int kt = 0; kt < nk; kt++) {
        const int buf = kt & 1;
        const bool more = (kt + 1 < nk);
        if (more) SGEMM_LDG((kt + 1) * BK);

        #pragma unroll
        for (int k = 0; k < BK; k++) {
            float4 a0 = *(const float4*)&As[buf][k][ty * 8];
            float4 a1 = *(const float4*)&As[buf][k][ty * 8 + 4];
            float4 b0 = *(const float4*)&Bs[buf][k][tx * 8];
            float4 b1 = *(const float4*)&Bs[buf][k][tx * 8 + 4];
            float av[8] = {a0.x, a0.y, a0.z, a0.w, a1.x, a1.y, a1.z, a1.w};
            float bv[8] = {b0.x, b0.y, b0.z, b0.w, b1.x, b1.y, b1.z, b1.w};
            #pragma unroll
            for (int i = 0; i < 8; i++)
                #pragma unroll
                for (int j = 0; j < 8; j++)
                    acc[i][j] = fmaf(av[i], bv[j], acc[i][j]);
        }
        if (more) SGEMM_STS(buf ^ 1);
        __syncthreads();
    }

    #pragma unroll
    for (int i = 0; i < 8; i++) {
        int gr = rowBase + ty * 8 + i;
        if (gr >= M) continue;
        int gc = colBase + tx * 8;
        if (gc < Ncols) {
            *(float4*)(g_h + (size_t)gr * Ncols + gc) =
                make_float4(acc[i][0], acc[i][1], acc[i][2], acc[i][3]);
            *(float4*)(g_h + (size_t)gr * Ncols + gc + 4) =
                make_float4(acc[i][4], acc[i][5], acc[i][6], acc[i][7]);
        }
    }
}

// ---------------------------------------------------------------------------
// K2: per-(node,head) attention scalars; also zeroes BN column stats
// ---------------------------------------------------------------------------
__global__ void alpha_kernel(const float* __restrict__ a_s, const float* __restrict__ a_d,
                             int M, int H) {
    int idx = blockIdx.x * blockDim.x + threadIdx.x;
    if (idx < HCMAX) { g_colsum[idx] = 0.f; g_colsq[idx] = 0.f; }
    if (idx >= M * H) return;
    int hh = idx % H;
    int n  = idx / H;
    const float4* hp = (const float4*)(g_h + (size_t)n * H * 64 + hh * 64);
    const float4* ap = (const float4*)(a_s + hh * 64);
    const float4* dp = (const float4*)(a_d + hh * 64);
    float s = 0.f, d = 0.f;
    #pragma unroll
    for (int i = 0; i < 16; i++) {
        float4 h4 = hp[i], a4 = ap[i], d4 = dp[i];
        s += h4.x * a4.x + h4.y * a4.y + h4.z * a4.z + h4.w * a4.w;
        d += h4.x * d4.x + h4.y * d4.y + h4.z * d4.z + h4.w * d4.w;
    }
    g_asn[idx] = s;
    g_adn[idx] = d;
}

// ---------------------------------------------------------------------------
// K3: fused GAT aggregation (H=4, HC=256). Warp per node. No atomics on g_out.
//     out = sum_e softmax(e)*h[src] + bias; BN stats accumulated in-block.
// ---------------------------------------------------------------------------
__device__ __forceinline__ float4 lrelu4(float4 v) {
    v.x = v.x > 0.f ? v.x : 0.2f * v.x;
    v.y = v.y > 0.f ? v.y : 0.2f * v.y;
    v.z = v.z > 0.f ? v.z : 0.2f * v.z;
    v.w = v.w > 0.f ? v.w : 0.2f * v.w;
    return v;
}

__global__ __launch_bounds__(256)
void aggregate4_kernel(const float* __restrict__ bias, int M) {
    __shared__ float s_c[256], s_q[256];
    int t = threadIdx.x;
    s_c[t] = 0.f; s_q[t] = 0.f;
    __syncthreads();

    int w = t >> 5, lane = t & 31;
    int n = blockIdx.x * 8 + w;
    if (n < M) {
        int r0 = g_rowptr[n], r1 = g_rowptr[n + 1];
        float4 d4 = *(const float4*)(g_adn + n * 4);

        // pass 1: segment max (lanes split edges)
        float4 mx = make_float4(-1e30f, -1e30f, -1e30f, -1e30f);
        for (int j = r0 + lane; j < r1; j += 32) {
            int s = g_csrsrc[j];
            float4 sv = *(const float4*)(g_asn + s * 4);
            float4 e = lrelu4(make_float4(sv.x + d4.x, sv.y + d4.y, sv.z + d4.z, sv.w + d4.w));
            mx.x = fmaxf(mx.x, e.x); mx.y = fmaxf(mx.y, e.y);
            mx.z = fmaxf(mx.z, e.z); mx.w = fmaxf(mx.w, e.w);
        }
        #pragma unroll
        for (int off = 16; off; off >>= 1) {
            mx.x = fmaxf(mx.x, __shfl_xor_sync(0xffffffffu, mx.x, off));
            mx.y = fmaxf(mx.y, __shfl_xor_sync(0xffffffffu, mx.y, off));
            mx.z = fmaxf(mx.z, __shfl_xor_sync(0xffffffffu, mx.z, off));
            mx.w = fmaxf(mx.w, __shfl_xor_sync(0xffffffffu, mx.w, off));
        }

        // pass 2: weighted accumulate (whole warp cooperates per edge)
        int head = lane >> 3;                      // lane owns cols [lane*8, lane*8+8)
        float4 acc0 = make_float4(0.f, 0.f, 0.f, 0.f);
        float4 acc1 = make_float4(0.f, 0.f, 0.f, 0.f);
        float4 sw   = make_float4(0.f, 0.f, 0.f, 0.f);
        for (int j = r0; j < r1; j++) {
            int s = g_csrsrc[j];
            float4 sv = *(const float4*)(g_asn + s * 4);
            float4 e = lrelu4(make_float4(sv.x + d4.x, sv.y + d4.y, sv.z + d4.z, sv.w + d4.w));
            float4 wv = make_float4(__expf(e.x - mx.x), __expf(e.y - mx.y),
                                    __expf(e.z - mx.z), __expf(e.w - mx.w));
            sw.x += wv.x; sw.y += wv.y; sw.z += wv.z; sw.w += wv.w;
            float wl = head == 0 ? wv.x : head == 1 ? wv.y : head == 2 ? wv.z : wv.w;
            const float4* hp = (const float4*)(g_h + (size_t)s * 256 + lane * 8);
            float4 h0 = hp[0], h1 = hp[1];
            acc0.x = fmaf(wl, h0.x, acc0.x); acc0.y = fmaf(wl, h0.y, acc0.y);
            acc0.z = fmaf(wl, h0.z, acc0.z); acc0.w = fmaf(wl, h0.w, acc0.w);
            acc1.x = fmaf(wl, h1.x, acc1.x); acc1.y = fmaf(wl, h1.y, acc1.y);
            acc1.z = fmaf(wl, h1.z, acc1.z); acc1.w = fmaf(wl, h1.w, acc1.w);
        }
        float swh = head == 0 ? sw.x : head == 1 ? sw.y : head == 2 ? sw.z : sw.w;
        float inv = 1.f / swh;
        int c = lane * 8;
        float4 b0 = *(const float4*)(bias + c);
        float4 b1 = *(const float4*)(bias + c + 4);
        float4 v0 = make_float4(acc0.x * inv + b0.x, acc0.y * inv + b0.y,
                                acc0.z * inv + b0.z, acc0.w * inv + b0.w);
        float4 v1 = make_float4(acc1.x * inv + b1.x, acc1.y * inv + b1.y,
                                acc1.z * inv + b1.z, acc1.w * inv + b1.w);
        *(float4*)(g_out + (size_t)n * 256 + c)     = v0;
        *(float4*)(g_out + (size_t)n * 256 + c + 4) = v1;

        atomicAdd(&s_c[c + 0], v0.x); atomicAdd(&s_q[c + 0], v0.x * v0.x);
        atomicAdd(&s_c[c + 1], v0.y); atomicAdd(&s_q[c + 1], v0.y * v0.y);
        atomicAdd(&s_c[c + 2], v0.z); atomicAdd(&s_q[c + 2], v0.z * v0.z);
        atomicAdd(&s_c[c + 3], v0.w); atomicAdd(&s_q[c + 3], v0.w * v0.w);
        atomicAdd(&s_c[c + 4], v1.x); atomicAdd(&s_q[c + 4], v1.x * v1.x);
        atomicAdd(&s_c[c + 5], v1.y); atomicAdd(&s_q[c + 5], v1.y * v1.y);
        atomicAdd(&s_c[c + 6], v1.z); atomicAdd(&s_q[c + 6], v1.z * v1.z);
        atomicAdd(&s_c[c + 7], v1.w); atomicAdd(&s_q[c + 7], v1.w * v1.w);
    }
    __syncthreads();
    atomicAdd(&g_colsum[t], s_c[t]);
    atomicAdd(&g_colsq[t],  s_q[t]);
}

// H=1, HC=64 variant
__global__ __launch_bounds__(256)
void aggregate1_kernel(const float* __restrict__ bias, int M) {
    __shared__ float s_c[64], s_q[64];
    int t = threadIdx.x;
    if (t < 64) { s_c[t] = 0.f; s_q[t] = 0.f; }
    __syncthreads();

    int w = t >> 5, lane = t & 31;
    int n = blockIdx.x * 8 + w;
    if (n < M) {
        int r0 = g_rowptr[n], r1 = g_rowptr[n + 1];
        float d = g_adn[n];
        float mx = -1e30f;
        for (int j = r0 + lane; j < r1; j += 32) {
            int s = g_csrsrc[j];
            float e = g_asn[s] + d;
            e = e > 0.f ? e : 0.2f * e;
            mx = fmaxf(mx, e);
        }
        #pragma unroll
        for (int off = 16; off; off >>= 1)
            mx = fmaxf(mx, __shfl_xor_sync(0xffffffffu, mx, off));

        float a0 = 0.f, a1 = 0.f, sw = 0.f;
        for (int j = r0; j < r1; j++) {
            int s = g_csrsrc[j];
            float e = g_asn[s] + d;
            e = e > 0.f ? e : 0.2f * e;
            float wv = __expf(e - mx);
            sw += wv;
            float2 h = *(const float2*)(g_h + (size_t)s * 64 + lane * 2);
            a0 = fmaf(wv, h.x, a0);
            a1 = fmaf(wv, h.y, a1);
        }
        float inv = 1.f / sw;
        int c = lane * 2;
        float v0 = a0 * inv + bias[c];
        float v1 = a1 * inv + bias[c + 1];
        *(float2*)(g_out + (size_t)n * 64 + c) = make_float2(v0, v1);
        atomicAdd(&s_c[c],     v0); atomicAdd(&s_q[c],     v0 * v0);
        atomicAdd(&s_c[c + 1], v1); atomicAdd(&s_q[c + 1], v1 * v1);
    }
    __syncthreads();
    if (t < 64) {
        atomicAdd(&g_colsum[t], s_c[t]);
        atomicAdd(&g_colsq[t],  s_q[t]);
    }
}

// ---------------------------------------------------------------------------
// K4: BN statistics -> per-column scale/shift
// ---------------------------------------------------------------------------
__global__ void bnstats_kernel(const float* __restrict__ gamma,
                               const float* __restrict__ beta, int M, int HC) {
    int c = threadIdx.x;
    if (c >= HC) return;
    float invM = 1.f / (float)M;
    float mean = g_colsum[c] * invM;
    float var  = g_colsq[c] * invM - mean * mean;
    float s    = gamma[c] * rsqrtf(var + 1e-5f);
    g_scale[c] = s;
    g_shift[c] = beta[c] - mean * s;
}

// ---------------------------------------------------------------------------
// K5: MLP head. warp/node: BN+ReLU(64) -> 32 (ReLU) -> 2
// ---------------------------------------------------------------------------
__global__ __launch_bounds__(256)
void mlp_kernel(const float* __restrict__ hw1, const float* __restrict__ hb1,
                const float* __restrict__ hw2, const float* __restrict__ hb2,
                float* __restrict__ out, int M) {
    __shared__ float sh[8][66];
    int w    = threadIdx.x >> 5;
    int lane = threadIdx.x & 31;
    int n    = blockIdx.x * 8 + w;
    if (n >= M) return;

    int c0 = lane * 2;
    float2 f = *(const float2*)(g_out + (size_t)n * 64 + c0);
    sh[w][c0]     = fmaxf(0.f, fmaf(f.x, g_scale[c0],     g_shift[c0]));
    sh[w][c0 + 1] = fmaxf(0.f, fmaf(f.y, g_scale[c0 + 1], g_shift[c0 + 1]));
    __syncwarp();

    float hj = hb1[lane];
    #pragma unroll
    for (int k = 0; k < 64; k++) hj = fmaf(sh[w][k], hw1[k * 32 + lane], hj);
    hj = fmaxf(hj, 0.f);

    float o0 = hj * hw2[lane * 2];
    float o1 = hj * hw2[lane * 2 + 1];
    #pragma unroll
    for (int off = 16; off; off >>= 1) {
        o0 += __shfl_down_sync(0xffffffffu, o0, off);
        o1 += __shfl_down_sync(0xffffffffu, o1, off);
    }
    if (lane == 0) {
        out[n * 2]     = o0 + hb2[0];
        out[n * 2 + 1] = o1 + hb2[1];
    }
}

// ---------------------------------------------------------------------------
// Host launcher
// ---------------------------------------------------------------------------
extern "C" void kernel_launch(void* const* d_in, const int* in_sizes, int n_in,
                              void* d_out, int out_size) {
    const float* x  = (const float*)d_in[0];
    const int*   ei = (const int*)d_in[1];
    const int M    = in_sizes[0] / 128;     // 50000
    const int E    = in_sizes[1] / 2;       // 400000
    const int Etot = E + M;

    // CSR (once; reused by all 4 layers)
    csr_zero <<<(M + 255) / 256, 256>>>(M);
    csr_count<<<(Etot + 255) / 256, 256>>>(ei, E, Etot);
    csr_scan <<<1, 1024>>>(M, Etot);
    csr_fill <<<(Etot + 255) / 256, 256>>>(ei, E, Etot);

    for (int l = 0; l < 4; l++) {
        const float* W  = (const float*)d_in[2 + l * 6 + 0];
        const float* as = (const float*)d_in[2 + l * 6 + 1];
        const float* ad = (const float*)d_in[2 + l * 6 + 2];
        const float* b  = (const float*)d_in[2 + l * 6 + 3];
        const float* gg = (const float*)d_in[2 + l * 6 + 4];
        const float* be = (const float*)d_in[2 + l * 6 + 5];
        const int H  = (l < 3) ? 4 : 1;
        const int HC = H * 64;
        const int K  = (l == 0) ? 128 : 256;

        dim3 ggrid((HC + BN - 1) / BN, (M + BM - 1) / BM);
        sgemm_kernel<<<ggrid, 256>>>(x, W, M, K, HC, l > 0 ? 1 : 0);

        alpha_kernel<<<(M * H + 255) / 256, 256>>>(as, ad, M, H);

        if (l < 3) aggregate4_kernel<<<(M + 7) / 8, 256>>>(b, M);
        else       aggregate1_kernel<<<(M + 7) / 8, 256>>>(b, M);

        bnstats_kernel<<<1, 256>>>(gg, be, M, HC);
    }

    mlp_kernel<<<(M + 7) / 8, 256>>>((const float*)d_in[26], (const float*)d_in[27],
                                     (const float*)d_in[28], (const float*)d_in[29],
                                     (float*)d_out, M);
}